// round 16
// baseline (speedup 1.0000x reference)
#include <cuda_runtime.h>

typedef unsigned long long u64;
typedef unsigned int u32;

#define NB      16
#define SS      4096
#define D4      128              // float4 per gmem row
#define MT      128              // segment rows per block
#define HALO    19
#define NROWS   147              // rows with real data (MT + HALO)
#define NROWS_S 152              // stored rows (B tiles reach m0+39 = 151)
#define RSTRIDE 1040             // bf16 row stride bytes (16B-aligned, ldmatrix conflict-free)
#define TILEB   (NROWS_S * RSTRIDE)     // 158080
#define DBANDO  TILEB                   // fp32 band offset
#define DST     42                      // band float stride
#define DBANDB  (MT * DST * 4)          // 21504
#define INVHO   (DBANDO + DBANDB)       // 179584 (float[19])
#define SMEMSZ  (INVHO + 128)
#define NTHR    512
#define NWARPS  16
#define NSEG    32               // 4096 / 128
#define NBLK    (NB * NSEG)      // 512
#define CNT_DIST 40815           // sum_{k=10}^{19} (4096 - k)

__device__ float2       g_part[NBLK];
__device__ unsigned int g_count = 0;

__device__ __forceinline__ u32 smem_u32(const void* p) {
    u32 a;
    asm("{ .reg .u64 t; cvta.to.shared.u64 t, %1; cvt.u32.u64 %0, t; }"
        : "=r"(a) : "l"(p));
    return a;
}
__device__ __forceinline__ u32 cvt2(float hi_src, float lo_src) {
    u32 d;
    asm("cvt.rn.bf16x2.f32 %0, %1, %2;" : "=r"(d) : "f"(hi_src), "f"(lo_src));
    return d;
}
__device__ __forceinline__ float wred(float v) {
    v += __shfl_xor_sync(0xffffffffu, v, 16);
    v += __shfl_xor_sync(0xffffffffu, v, 8);
    v += __shfl_xor_sync(0xffffffffu, v, 4);
    v += __shfl_xor_sync(0xffffffffu, v, 2);
    v += __shfl_xor_sync(0xffffffffu, v, 1);
    return v;
}
__device__ __forceinline__ void ldsm_x4(u32& r0, u32& r1, u32& r2, u32& r3, u32 addr) {
    asm volatile("ldmatrix.sync.aligned.m8n8.x4.shared.b16 {%0,%1,%2,%3}, [%4];"
                 : "=r"(r0), "=r"(r1), "=r"(r2), "=r"(r3) : "r"(addr));
}
__device__ __forceinline__ void ldsm_x2(u32& r0, u32& r1, u32 addr) {
    asm volatile("ldmatrix.sync.aligned.m8n8.x2.shared.b16 {%0,%1}, [%2];"
                 : "=r"(r0), "=r"(r1) : "r"(addr));
}
__device__ __forceinline__ void mma16816(float* c, u32 a0, u32 a1, u32 a2, u32 a3,
                                         u32 b0, u32 b1) {
    asm volatile(
        "mma.sync.aligned.m16n8k16.row.col.f32.bf16.bf16.f32 "
        "{%0,%1,%2,%3}, {%4,%5,%6,%7}, {%8,%9}, {%0,%1,%2,%3};"
        : "+f"(c[0]), "+f"(c[1]), "+f"(c[2]), "+f"(c[3])
        : "r"(a0), "r"(a1), "r"(a2), "r"(a3), "r"(b0), "r"(b1));
}

extern __shared__ char smemc[];   // [bf16 tile | fp32 D band | invh]

__global__ void __launch_bounds__(NTHR, 1)
tcl_main(const float* __restrict__ hs, float* __restrict__ out) {
    const int seg  = blockIdx.x;
    const int b    = blockIdx.y;
    const int t0   = seg * MT;
    const int tid  = threadIdx.x;
    const int wid  = tid >> 5;
    const int lane = tid & 31;

    const u32 sb = smem_u32(smemc);
    float* Db   = reinterpret_cast<float*>(smemc + DBANDO);
    float* invh = reinterpret_cast<float*>(smemc + INVHO);
    const float4* __restrict__ hb4 =
        reinterpret_cast<const float4*>(hs) + (size_t)b * SS * D4;

    // ── load: fp32 gmem -> bf16 rows in smem (152 rows; OOB rows zero) ──
    for (int idx = tid; idx < NROWS_S * D4; idx += NTHR) {
        int row = idx >> 7;
        int c4  = idx & 127;
        int g   = t0 + row;
        float4 v = (g < SS) ? hb4[(size_t)g * D4 + c4]
                            : make_float4(0.f, 0.f, 0.f, 0.f);
        uint2 cc;
        cc.x = cvt2(v.y, v.x);
        cc.y = cvt2(v.w, v.z);
        *reinterpret_cast<uint2*>(smemc + (size_t)row * RSTRIDE + c4 * 8) = cc;
    }
    __syncthreads();

    if (wid < 8) {
        // ── MMA warps: D[16 x 40] Gram band for rows m0..m0+15 ──────────
        const int m0 = wid * 16;
        const int q  = lane >> 3;
        u32 aaddr = sb + (u32)(m0 + (lane & 7) + 8 * (q & 1)) * RSTRIDE
                  + 16u * (u32)(q >> 1);
        u32 baddr[5];
#pragma unroll
        for (int j = 0; j < 5; ++j)
            baddr[j] = sb + (u32)(m0 + 8 * j + (lane & 7)) * RSTRIDE
                     + 16u * (u32)(q & 1);

        float c[5][4];
#pragma unroll
        for (int j = 0; j < 5; ++j)
#pragma unroll
            for (int e = 0; e < 4; ++e) c[j][e] = 0.f;

#pragma unroll 4
        for (int kt = 0; kt < 32; ++kt) {
            u32 a0, a1, a2, a3;
            ldsm_x4(a0, a1, a2, a3, aaddr);
            aaddr += 32;
#pragma unroll
            for (int j = 0; j < 5; ++j) {
                u32 b0, b1;
                ldsm_x2(b0, b1, baddr[j]);
                baddr[j] += 32;
                mma16816(c[j], a0, a1, a2, a3, b0, b1);
            }
        }

        // dump accumulators into the band: Db[m][j] = G[m][m0 + j]
        const int ra   = m0 + (lane >> 2);
        const int col0 = (lane & 3) * 2;
#pragma unroll
        for (int j = 0; j < 5; ++j) {
            *reinterpret_cast<float2*>(&Db[(size_t)ra * DST + 8 * j + col0])
                = make_float2(c[j][0], c[j][1]);
            *reinterpret_cast<float2*>(&Db[(size_t)(ra + 8) * DST + 8 * j + col0])
                = make_float2(c[j][2], c[j][3]);
        }
    } else {
        // ── halo-norm warps: rows 128..146 (fp32 dot of bf16 row) ───────
        for (int r = MT + (wid - 8); r < NROWS; r += 8) {
            const uint4* rp = reinterpret_cast<const uint4*>(
                smemc + (size_t)r * RSTRIDE);
            uint4 v0 = rp[lane];
            uint4 v1 = rp[lane + 32];
            float acc = 0.f;
            u32 w[8] = {v0.x, v0.y, v0.z, v0.w, v1.x, v1.y, v1.z, v1.w};
#pragma unroll
            for (int j = 0; j < 8; ++j) {
                float hi = __uint_as_float(w[j] & 0xFFFF0000u);
                float lo = __uint_as_float(w[j] << 16);
                acc += hi * hi + lo * lo;
            }
            float s = wred(acc);
            if (lane == 0) invh[r - MT] = rsqrtf(s);
        }
    }
    __syncthreads();

    // ── sims from the Gram band (diag = norms, free) ─────────────────────
    float accA = 0.f, accD = 0.f;
    if (tid < MT) {
        const int m = tid;
        const float* Dm = Db + (size_t)m * DST;
        const int base = m & 15;
        float invm = rsqrtf(Dm[base]);
        {   // k = 1
            int n = m + 1;
            float invn = (n < MT) ? rsqrtf(Db[(size_t)n * DST + (n & 15)])
                                  : invh[n - MT];
            float sim = Dm[base + 1] * invm * invn;
            if (t0 + n < SS) accA = sim;
        }
#pragma unroll
        for (int k = 10; k <= 19; ++k) {
            int n = m + k;
            float invn = (n < MT) ? rsqrtf(Db[(size_t)n * DST + (n & 15)])
                                  : invh[n - MT];
            float sim = Dm[base + k] * invm * invn;
            float cc  = fmaxf(0.5f - sim, 0.f);
            if (t0 + n < SS) accD += cc;
        }
    }

    // ── block combine + grid ticket reduction ────────────────────────────
    float aWarp = wred(accA);
    float dWarp = wred(accD);

    __shared__ float rA[NWARPS], rD[NWARPS];
    __shared__ int   sLast;
    if (lane == 0) { rA[wid] = aWarp; rD[wid] = dWarp; }
    __syncthreads();
    if (tid == 0) {
        float sA = 0.f, sD = 0.f;
#pragma unroll
        for (int w = 0; w < NWARPS; ++w) { sA += rA[w]; sD += rD[w]; }
        g_part[b * NSEG + seg] = make_float2(sA, sD);
        __threadfence();
        unsigned t = atomicAdd(&g_count, 1u);
        sLast = (t == NBLK - 1);
    }
    __syncthreads();

    if (sLast && tid < 32) {
        __threadfence();
        const float* gp = reinterpret_cast<const float*>(g_part);
        float a = 0.f, dd = 0.f;
        for (int i = tid; i < NBLK; i += 32) {
            a  += __ldcg(gp + 2 * i);
            dd += __ldcg(gp + 2 * i + 1);
        }
        a  = wred(a);
        dd = wred(dd);
        if (tid == 0) {
            float adj  = 1.f - a / ((float)NB * (float)(SS - 1));
            float dist = dd / ((float)NB * (float)CNT_DIST);
            out[0] = adj + dist;
            g_count = 0;                      // reset for next graph replay
        }
    }
}

extern "C" void kernel_launch(void* const* d_in, const int* in_sizes, int n_in,
                              void* d_out, int out_size) {
    (void)in_sizes; (void)n_in; (void)out_size;
    const float* hs = (const float*)d_in[0];

    cudaFuncSetAttribute(tcl_main, cudaFuncAttributeMaxDynamicSharedMemorySize,
                         SMEMSZ);

    dim3 grid(NSEG, NB);
    tcl_main<<<grid, NTHR, SMEMSZ>>>(hs, (float*)d_out);
}